// round 5
// baseline (speedup 1.0000x reference)
#include <cuda_runtime.h>
#include <cuda_bf16.h>
#include <cstdint>

#define NN   4096
#define DIN  512
#define HID  256
#define DBOX 22

// ---- scratch (device globals) ----
__device__ __nv_bfloat16 g_xb[NN * DIN];
__device__ __nv_bfloat16 g_Wb[6][DIN * HID];    // W in bf16, [k][n] as given
__device__ __nv_bfloat16 g_Kb[2][NN * HID];
__device__ __nv_bfloat16 g_Qb[2][NN * HID];
__device__ __nv_bfloat16 g_Vb[2][NN * HID];
__device__ __nv_bfloat16 g_BMb[2][NN * 32];     // box@M, zero-padded to 32 cols
__device__ __nv_bfloat16 g_boxb[NN * 32];       // box, zero-padded to 32 cols
__device__ float g_M[2][DBOX * DBOX];
__device__ float g_O[2][NN * HID];
__device__ float g_part[2][64];
__device__ float g_isum[2];

// ================= PTX helpers =====================================================
__device__ __forceinline__ uint32_t s2u(const void* p) {
    uint32_t a;
    asm("{ .reg .u64 t; cvta.to.shared.u64 t, %1; cvt.u32.u64 %0, t; }" : "=r"(a) : "l"(p));
    return a;
}
__device__ __forceinline__ void cp16(uint32_t s, const void* g) {
    asm volatile("cp.async.cg.shared.global [%0], [%1], 16;" :: "r"(s), "l"(g));
}
#define CP_COMMIT asm volatile("cp.async.commit_group;" ::: "memory")
#define CP_WAIT0  asm volatile("cp.async.wait_group 0;"  ::: "memory")
#define CP_WAIT1  asm volatile("cp.async.wait_group 1;"  ::: "memory")

__device__ __forceinline__ void ldsm4(uint32_t* r, uint32_t a) {
    asm volatile("ldmatrix.sync.aligned.m8n8.x4.shared.b16 {%0,%1,%2,%3}, [%4];"
                 : "=r"(r[0]), "=r"(r[1]), "=r"(r[2]), "=r"(r[3]) : "r"(a));
}
__device__ __forceinline__ void ldsm4t(uint32_t* r, uint32_t a) {
    asm volatile("ldmatrix.sync.aligned.m8n8.x4.trans.shared.b16 {%0,%1,%2,%3}, [%4];"
                 : "=r"(r[0]), "=r"(r[1]), "=r"(r[2]), "=r"(r[3]) : "r"(a));
}
__device__ __forceinline__ void mma16816(float* d, const uint32_t* a, const uint32_t* b) {
    asm volatile(
        "mma.sync.aligned.m16n8k16.row.col.f32.bf16.bf16.f32 "
        "{%0,%1,%2,%3}, {%4,%5,%6,%7}, {%8,%9}, {%0,%1,%2,%3};"
        : "+f"(d[0]), "+f"(d[1]), "+f"(d[2]), "+f"(d[3])
        : "r"(a[0]), "r"(a[1]), "r"(a[2]), "r"(a[3]), "r"(b[0]), "r"(b[1]));
}
__device__ __forceinline__ uint32_t packbf2(float x, float y) {
    __nv_bfloat162 p = __floats2bfloat162_rn(x, y);
    return *(uint32_t*)&p;
}

// ================= conversions ====================================================
__global__ __launch_bounds__(256) void conv_x(const float* __restrict__ x) {
    int idx = blockIdx.x * 256 + threadIdx.x;          // float4 index
    float4 v = ((const float4*)x)[idx];
    *(uint32_t*)&g_xb[idx * 4]     = packbf2(v.x, v.y);
    *(uint32_t*)&g_xb[idx * 4 + 2] = packbf2(v.z, v.w);
}

__global__ __launch_bounds__(256) void conv_w(
    const float* __restrict__ W0, const float* __restrict__ W1, const float* __restrict__ W2,
    const float* __restrict__ W3, const float* __restrict__ W4, const float* __restrict__ W5) {
    const int z = blockIdx.z;
    const float* W = (z == 0) ? W0 : (z == 1) ? W1 : (z == 2) ? W2 : (z == 3) ? W3 : (z == 4) ? W4 : W5;
    int idx = blockIdx.x * 256 + threadIdx.x;          // float4 index over 512*256/4
    float4 v = ((const float4*)W)[idx];
    *(uint32_t*)&g_Wb[z][idx * 4]     = packbf2(v.x, v.y);
    *(uint32_t*)&g_Wb[z][idx * 4 + 2] = packbf2(v.z, v.w);
}

// ================= M = WG @ WG^T (22x22, fp32) ====================================
__global__ void gramm_kernel(const float* __restrict__ WG1, const float* __restrict__ WG2) {
    const float* WG = blockIdx.x ? WG2 : WG1;
    int t = threadIdx.x;
    if (t < DBOX * DBOX) {
        int i = t / DBOX, j = t % DBOX;
        float s = 0.f;
        for (int d = 0; d < HID; ++d) s += WG[i * HID + d] * WG[j * HID + d];
        g_M[blockIdx.x][t] = s;
    }
}

// ================= pad box / BM -> [4096,32] bf16 =================================
__global__ __launch_bounds__(256) void pad_kernel(const float* __restrict__ box) {
    __shared__ float Ms[DBOX * DBOX];
    int y = blockIdx.y, t = threadIdx.x;   // y: 0=box, 1=BM br0, 2=BM br1
    if (y > 0) {
        for (int i = t; i < DBOX * DBOX; i += 256) Ms[i] = g_M[y - 1][i];
        __syncthreads();
    }
    int e = blockIdx.x * 256 + t;          // 4096*32 total, grid.x = 512
    int r = e >> 5, c = e & 31;
    float v = 0.f;
    if (c < DBOX) {
        if (y == 0) v = box[r * DBOX + c];
        else {
            float s = 0.f;
#pragma unroll
            for (int k = 0; k < DBOX; ++k) s += box[r * DBOX + k] * Ms[k * DBOX + c];
            v = s;
        }
    }
    __nv_bfloat16 h = __float2bfloat16(v);
    if (y == 0) g_boxb[e] = h;
    else g_BMb[y - 1][e] = h;
}

// ================= projection: C[4096,256] = xb @ W  (mma.sync bf16) ==============
__global__ void __launch_bounds__(256, 1) proj_kernel(int) {
    extern __shared__ char smem[];
    const int z = blockIdx.z;
    const int m0 = blockIdx.x * 128, n0 = blockIdx.y * 64;
    const int br = z / 3, wh = z % 3;
    __nv_bfloat16* C = (wh == 0) ? g_Kb[br] : (wh == 1) ? g_Qb[br] : g_Vb[br];
    const __nv_bfloat16* __restrict__ Wb = g_Wb[z];
    const int t = threadIdx.x, w = t >> 5, lane = t & 31;
    uint32_t sb = s2u(smem);
    const int mi = w >> 1, njw = w & 1;
    float acc[2][4][4] = {};

#define PROJ_ISSUE(ck)                                                               \
    {                                                                                \
        int k0 = (ck) * 64, buf = (ck) & 1;                                          \
        _Pragma("unroll") for (int l = 0; l < 4; ++l) {                              \
            int idx = t + l * 256;                                                   \
            int r = idx >> 3, c8 = (idx & 7) << 3;                                   \
            cp16(sb + buf * 18432 + (r * 72 + c8) * 2, g_xb + (m0 + r) * DIN + k0 + c8); \
        }                                                                            \
        _Pragma("unroll") for (int l = 0; l < 2; ++l) {                              \
            int idx = t + l * 256;                                                   \
            int r = idx >> 3, c8 = (idx & 7) << 3;                                   \
            cp16(sb + 36864 + buf * 9216 + (r * 72 + c8) * 2, Wb + (k0 + r) * HID + n0 + c8); \
        }                                                                            \
        CP_COMMIT;                                                                   \
    }

    PROJ_ISSUE(0);
    for (int ck = 0; ck < 8; ++ck) {
        if (ck < 7) { PROJ_ISSUE(ck + 1); CP_WAIT1; } else { CP_WAIT0; }
        __syncthreads();
        const uint32_t aB = sb + (ck & 1) * 18432;
        const uint32_t bB = sb + 36864 + (ck & 1) * 9216;
#pragma unroll
        for (int kt = 0; kt < 4; ++kt) {
            uint32_t a[2][4];
#pragma unroll
            for (int mt = 0; mt < 2; ++mt) {
                int row = mi * 32 + mt * 16 + (lane & 15);
                int col = kt * 16 + ((lane >> 4) << 3);
                ldsm4(a[mt], aB + (row * 72 + col) * 2);
            }
#pragma unroll
            for (int nb = 0; nb < 2; ++nb) {
                uint32_t bw[4];
                int wrow = kt * 16 + ((lane >> 3) & 1) * 8 + (lane & 7);
                int wcol = njw * 32 + nb * 16 + ((lane >> 4) << 3);
                ldsm4t(bw, bB + (wrow * 72 + wcol) * 2);
#pragma unroll
                for (int mt = 0; mt < 2; ++mt) {
                    mma16816(acc[mt][nb * 2],     a[mt], bw);
                    mma16816(acc[mt][nb * 2 + 1], a[mt], bw + 2);
                }
            }
        }
        __syncthreads();
    }
#pragma unroll
    for (int mt = 0; mt < 2; ++mt)
#pragma unroll
        for (int nt = 0; nt < 4; ++nt) {
            int row = m0 + mi * 32 + mt * 16 + (lane >> 2);
            int col = n0 + njw * 32 + nt * 8 + (lane & 3) * 2;
            *(uint32_t*)&C[row * HID + col]       = packbf2(acc[mt][nt][0], acc[mt][nt][1]);
            *(uint32_t*)&C[(row + 8) * HID + col] = packbf2(acc[mt][nt][2], acc[mt][nt][3]);
        }
}

// ================= fused attention: FA2-style register-fragment S =================
// 8 warps: mi = w>>1 (m16 rows), jh2 = w&1 (j32 k-slice in both GEMMs).
// smem map (bytes):
//   sK   [64][264] @0        33792
//   sBM  [64][40]  @33792     5120
//   sQ 2x[64][264] @38912    67584   (reused as O-reduce buffer [64][256] f32)
//   sBox 2x[64][40]@106496   10240
//   sV 2x[64][264] @116736   67584
//   sred           @184320    1024   -> total 185344
__global__ void __launch_bounds__(256, 1) attn_kernel(int) {
    extern __shared__ char smem[];
    const int b = blockIdx.y;
    const int i0 = blockIdx.x * 64;
    const int t = threadIdx.x, w = t >> 5, lane = t & 31;
    uint32_t sb = s2u(smem);
    const __nv_bfloat16* __restrict__ Kg = g_Kb[b];
    const __nv_bfloat16* __restrict__ Qg = g_Qb[b];
    const __nv_bfloat16* __restrict__ Vg = g_Vb[b];
    const __nv_bfloat16* __restrict__ BMg = g_BMb[b];

    const int mi = w >> 1, jh2 = w & 1;
    float acc[32][4] = {};          // O-partial: m16 x d256, 32 n8-tiles
    uint32_t agm[2][4];             // gate A-frags (BM), k=32: loaded once
    float sumLoc = 0.f;

    // ---- prologue loads ----
#pragma unroll
    for (int l = 0; l < 8; ++l) {
        int idx = t + l * 256;
        int r = idx >> 5, c8 = (idx & 31) << 3;
        cp16(sb + (r * 264 + c8) * 2, Kg + (i0 + r) * HID + c8);
    }
    { int r = t >> 2, c8 = (t & 3) << 3;
      cp16(sb + 33792 + (r * 40 + c8) * 2, BMg + (i0 + r) * 32 + c8); }
    CP_COMMIT;

#define ATTN_ISSUE(j0, buf)                                                          \
    {                                                                                \
        _Pragma("unroll") for (int l = 0; l < 8; ++l) {                              \
            int idx = t + l * 256;                                                   \
            int r = idx >> 5, c8 = (idx & 31) << 3;                                  \
            cp16(sb + 38912 + (buf) * 33792 + (r * 264 + c8) * 2, Qg + ((j0) + r) * HID + c8); \
        }                                                                            \
        _Pragma("unroll") for (int l = 0; l < 8; ++l) {                              \
            int idx = t + l * 256;                                                   \
            int r = idx >> 5, c8 = (idx & 31) << 3;                                  \
            cp16(sb + 116736 + (buf) * 33792 + (r * 264 + c8) * 2, Vg + ((j0) + r) * HID + c8); \
        }                                                                            \
        { int r = t >> 2, c8 = (t & 3) << 3;                                         \
          cp16(sb + 106496 + (buf) * 5120 + (r * 40 + c8) * 2, g_boxb + ((j0) + r) * 32 + c8); } \
        CP_COMMIT;                                                                   \
    }
    ATTN_ISSUE(0, 0);
    ATTN_ISSUE(64, 1);

#pragma unroll 1
    for (int jt = 0; jt < 64; ++jt) {
        const int cur = jt & 1;
        CP_WAIT1;                  // tiles for jt (and K/BM on jt=0) resident
        __syncthreads();
        const uint32_t qB = sb + 38912 + cur * 33792;
        const uint32_t xB = sb + 106496 + cur * 5120;
        const uint32_t vB = sb + 116736 + cur * 33792;

        if (jt == 0) {             // hoist gate A-frags (persistent regs)
#pragma unroll
            for (int kt = 0; kt < 2; ++kt) {
                int row = mi * 16 + (lane & 15);
                int col = kt * 16 + ((lane >> 4) << 3);
                ldsm4(agm[kt], sb + 33792 + (row * 40 + col) * 2);
            }
        }

        // ---- stage 1: wa = K_i . Q_j^T (k=256) over this warp's j32 slice ----
        float wa[4][4] = {};
        float gg[4][4] = {};
#pragma unroll
        for (int kt = 0; kt < 16; ++kt) {
            uint32_t a[4], bq0[4], bq1[4];
            {
                int row = mi * 16 + (lane & 15);
                int col = kt * 16 + ((lane >> 4) << 3);
                ldsm4(a, sb + (row * 264 + col) * 2);
            }
            {
                int brow = jh2 * 32 + ((lane >> 4) << 3) + (lane & 7);
                int bcol = kt * 16 + ((lane >> 3) & 1) * 8;
                ldsm4(bq0, qB + (brow * 264 + bcol) * 2);
                ldsm4(bq1, qB + ((brow + 16) * 264 + bcol) * 2);
            }
            mma16816(wa[0], a, bq0);
            mma16816(wa[1], a, bq0 + 2);
            mma16816(wa[2], a, bq1);
            mma16816(wa[3], a, bq1 + 2);
        }
        // ---- gate: gg = BM_i . box_j^T (k=32) ----
#pragma unroll
        for (int kt = 0; kt < 2; ++kt) {
            uint32_t bx0[4], bx1[4];
            int brow = jh2 * 32 + ((lane >> 4) << 3) + (lane & 7);
            int bcol = kt * 16 + ((lane >> 3) & 1) * 8;
            ldsm4(bx0, xB + (brow * 40 + bcol) * 2);
            ldsm4(bx1, xB + ((brow + 16) * 40 + bcol) * 2);
            mma16816(gg[0], agm[kt], bx0);
            mma16816(gg[1], agm[kt], bx0 + 2);
            mma16816(gg[2], agm[kt], bx1);
            mma16816(gg[3], agm[kt], bx1 + 2);
        }

        // ---- elementwise in regs: S = relu(G/16) * exp(WA/16); pack to A-frags ----
        uint32_t sf[2][4];
#pragma unroll
        for (int nb = 0; nb < 4; ++nb) {
            float s[4];
#pragma unroll
            for (int q = 0; q < 4; ++q) {
                float gv = gg[nb][q];
                s[q] = gv > 0.f ? gv * 0.0625f * __expf(wa[nb][q] * 0.0625f) : 0.f;
                sumLoc += s[q];
            }
            sf[nb >> 1][(nb & 1) * 2]     = packbf2(s[0], s[1]);
            sf[nb >> 1][(nb & 1) * 2 + 1] = packbf2(s[2], s[3]);
        }

        // ---- stage 2: O-partial += S(m16 x j32) @ V(j32 x d256) ----
#pragma unroll
        for (int kt2 = 0; kt2 < 2; ++kt2) {
            int vrow = jh2 * 32 + kt2 * 16 + ((lane >> 3) & 1) * 8 + (lane & 7);
#pragma unroll
            for (int nb = 0; nb < 16; ++nb) {
                uint32_t bv[4];
                int vcol = nb * 16 + ((lane >> 4) << 3);
                ldsm4t(bv, vB + (vrow * 264 + vcol) * 2);
                mma16816(acc[nb * 2],     sf[kt2], bv);
                mma16816(acc[nb * 2 + 1], sf[kt2], bv + 2);
            }
        }
        __syncthreads();           // all warps done with buf 'cur'
        ATTN_ISSUE(((jt + 2) & 63) * 64, cur);
    }

    // ---- epilogue: cross-pair O reduce (j-halves) via smem, write g_O ----
    CP_WAIT0;
    __syncthreads();
    float* smemO = (float*)(smem + 38912);    // [64][256] f32
    if (jh2 == 0) {
#pragma unroll
        for (int nb = 0; nb < 32; ++nb) {
            int row = mi * 16 + (lane >> 2);
            int col = nb * 8 + (lane & 3) * 2;
            *(float2*)&smemO[row * 256 + col]       = make_float2(acc[nb][0], acc[nb][1]);
            *(float2*)&smemO[(row + 8) * 256 + col] = make_float2(acc[nb][2], acc[nb][3]);
        }
    }
    __syncthreads();
    if (jh2 == 1) {
#pragma unroll
        for (int nb = 0; nb < 32; ++nb) {
            int row = mi * 16 + (lane >> 2);
            int col = nb * 8 + (lane & 3) * 2;
            float2 p0 = *(float2*)&smemO[row * 256 + col];
            float2 p1 = *(float2*)&smemO[(row + 8) * 256 + col];
            *(float2*)&g_O[b][(i0 + row) * HID + col] =
                make_float2(p0.x + acc[nb][0], p0.y + acc[nb][1]);
            *(float2*)&g_O[b][(i0 + row + 8) * HID + col] =
                make_float2(p1.x + acc[nb][2], p1.y + acc[nb][3]);
        }
    }

    // ---- deterministic partial sum ----
    float* sred = (float*)(smem + 184320);
    sred[t] = sumLoc;
    __syncthreads();
    for (int s2 = 128; s2 > 0; s2 >>= 1) {
        if (t < s2) sred[t] += sred[t + s2];
        __syncthreads();
    }
    if (t == 0) g_part[b][blockIdx.x] = sred[0];
}

// ================= final sum -> 0.1/sum ===========================================
__global__ void sum_kernel() {
    if (threadIdx.x == 0) {
        float s = 0.f;
        for (int i = 0; i < 64; ++i) s += g_part[blockIdx.x][i];
        g_isum[blockIdx.x] = 0.1f / s;
    }
}

// ================= out = x + 0.1 * O/sum ==========================================
__global__ __launch_bounds__(256) void final_kernel(const float* __restrict__ x,
                                                    float* __restrict__ out) {
    int idx = blockIdx.x * 256 + threadIdx.x;
    int r = idx >> 9, c = idx & 511;
    int b = c >> 8, cc = c & 255;
    out[idx] = fmaf(g_O[b][r * HID + cc], g_isum[b], x[idx]);
}

// =================================================================================
extern "C" void kernel_launch(void* const* d_in, const int* in_sizes, int n_in,
                              void* d_out, int out_size) {
    const float* x   = (const float*)d_in[0];
    const float* box = (const float*)d_in[1];
    const float* WG1 = (const float*)d_in[2];
    const float* WK1 = (const float*)d_in[3];
    const float* WQ1 = (const float*)d_in[4];
    const float* WV1 = (const float*)d_in[5];
    const float* WG2 = (const float*)d_in[6];
    const float* WK2 = (const float*)d_in[7];
    const float* WQ2 = (const float*)d_in[8];
    const float* WV2 = (const float*)d_in[9];
    float* out = (float*)d_out;

    static int inited = 0;
    if (!inited) {
        cudaFuncSetAttribute(proj_kernel, cudaFuncAttributeMaxDynamicSharedMemorySize, 55296);
        cudaFuncSetAttribute(attn_kernel, cudaFuncAttributeMaxDynamicSharedMemorySize, 185344);
        inited = 1;
    }

    conv_x<<<2048, 256>>>(x);
    conv_w<<<dim3(128, 1, 6), 256>>>(WK1, WQ1, WV1, WK2, WQ2, WV2);
    gramm_kernel<<<2, 512>>>(WG1, WG2);
    pad_kernel<<<dim3(512, 3), 256>>>(box);
    proj_kernel<<<dim3(32, 4, 6), 256, 55296>>>(0);
    attn_kernel<<<dim3(64, 2), 256, 185344>>>(0);
    sum_kernel<<<2, 32>>>();
    final_kernel<<<8192, 256>>>(x, out);
}